// round 1
// baseline (speedup 1.0000x reference)
#include <cuda_runtime.h>
#include <cstdint>

// Problem constants (fixed by the dataset)
#define NN 200000
#define NE 6400000
#define NL 10

// ---------------- scratch (static __device__ — no allocations) -------------
__device__ int2   g_edges[NE];    // packed (src, dst) as int32 — 51.2 MB, L2-resident
__device__ int    g_deg[NN];
__device__ float  g_dis[NN];      // rsqrt(deg + 1)
__device__ float2 g_h[2][NN];     // ping-pong node state
__device__ float2 g_t[NN];        // t[n] = (h[n] @ W) * dis[n]
__device__ int    g_is64;         // edge_index element width flag

// ---------------- dtype sniff: int64 vs int32 edge_index -------------------
// int64 indices < 2^31 -> every odd 32-bit word is 0. int32 index data is
// uniform in [0, 200000): P(1024 odd words all zero) ~ (1/2e5)^1024 ~ 0.
__global__ void k_detect(const unsigned int* __restrict__ w) {
    int lane = threadIdx.x;          // 32 lanes, each checks 32 odd words
    unsigned int acc = 0;
    for (int i = 0; i < 32; i++)
        acc |= w[2 * (lane * 32 + i) + 1];
    unsigned mask = __ballot_sync(0xFFFFFFFFu, acc != 0);
    if (lane == 0) g_is64 = (mask == 0) ? 1 : 0;
}

__global__ void k_zero_deg() {
    int i = blockIdx.x * blockDim.x + threadIdx.x;
    if (i < NN) g_deg[i] = 0;
}

// Repack edges to int2 + count in-degree at dst
__global__ void k_pack(const void* __restrict__ ei_raw) {
    int e = blockIdx.x * blockDim.x + threadIdx.x;
    if (e >= NE) return;
    int s, d;
    if (g_is64) {
        const long long* ei = (const long long*)ei_raw;
        s = (int)ei[e];
        d = (int)ei[NE + e];
    } else {
        const int* ei = (const int*)ei_raw;
        s = ei[e];
        d = ei[NE + e];
    }
    g_edges[e] = make_int2(s, d);
    atomicAdd(&g_deg[d], 1);
}

// dis = rsqrt(deg + 1)   (self-loop guarantees deg >= 1), and copy x -> h[0]
__global__ void k_dis_init(const float* __restrict__ x) {
    int n = blockIdx.x * blockDim.x + threadIdx.x;
    if (n >= NN) return;
    g_dis[n] = rsqrtf((float)(g_deg[n] + 1));
    g_h[0][n] = make_float2(x[2 * n], x[2 * n + 1]);
}

// Per-node: t = (h @ W) * dis ; h_out = b + t*dis  (self-loop term, no zeroing)
__global__ void k_node(const float* __restrict__ Ws, const float* __restrict__ bs,
                       int layer, int inbuf) {
    int n = blockIdx.x * blockDim.x + threadIdx.x;
    if (n >= NN) return;
    const float* W = Ws + layer * 4;
    float w00 = __ldg(&W[0]), w01 = __ldg(&W[1]);
    float w10 = __ldg(&W[2]), w11 = __ldg(&W[3]);
    float b0 = __ldg(&bs[layer * 2 + 0]), b1 = __ldg(&bs[layer * 2 + 1]);
    float2 h = g_h[inbuf][n];
    float  d = g_dis[n];
    float tx = (h.x * w00 + h.y * w10) * d;
    float ty = (h.x * w01 + h.y * w11) * d;
    g_t[n] = make_float2(tx, ty);
    g_h[inbuf ^ 1][n] = make_float2(b0 + tx * d, b1 + ty * d);
}

// Per-edge scatter: h_out[dst] += t[src] * dis[dst]   (vector RED, sm_90+)
__global__ void k_edge(int outbuf) {
    int e = blockIdx.x * blockDim.x + threadIdx.x;
    if (e >= NE) return;
    int2  ed = g_edges[e];
    float2 t = __ldg(&g_t[ed.x]);
    float  d = __ldg(&g_dis[ed.y]);
    atomicAdd(&g_h[outbuf][ed.y], make_float2(t.x * d, t.y * d));
}

// out is h.T : out[f*N + n] = h[n].f
__global__ void k_out(float* __restrict__ out, int buf) {
    int n = blockIdx.x * blockDim.x + threadIdx.x;
    if (n >= NN) return;
    float2 h = g_h[buf][n];
    out[n]      = h.x;
    out[NN + n] = h.y;
}

extern "C" void kernel_launch(void* const* d_in, const int* in_sizes, int n_in,
                              void* d_out, int out_size) {
    const float* x  = (const float*)d_in[0];
    const void*  ei = d_in[1];
    const float* Ws = (const float*)d_in[2];
    const float* bs = (const float*)d_in[3];
    float* out = (float*)d_out;

    const int TB = 256;
    const int NB_N = (NN + TB - 1) / TB;
    const int NB_E = (NE + TB - 1) / TB;

    k_detect<<<1, 32>>>((const unsigned int*)ei);
    k_zero_deg<<<NB_N, TB>>>();
    k_pack<<<NB_E, TB>>>(ei);
    k_dis_init<<<NB_N, TB>>>(x);

    int inbuf = 0;
    for (int l = 0; l < NL; l++) {
        k_node<<<NB_N, TB>>>(Ws, bs, l, inbuf);
        k_edge<<<NB_E, TB>>>(inbuf ^ 1);
        inbuf ^= 1;
    }
    k_out<<<NB_N, TB>>>(out, inbuf);
}

// round 2
// speedup vs baseline: 1.5534x; 1.5534x over previous
#include <cuda_runtime.h>
#include <cstdint>

#define NN 200000
#define NE 6400000
#define NL 10
#define NB_N 782          // ceil(NN/256)

// ---------------- scratch (static __device__, no allocs) -------------------
__device__ int    g_csr[NE];       // src ids, grouped by dst (25.6 MB)
__device__ int    g_row[NN + 1];   // CSR row pointers (exclusive prefix of deg)
__device__ int    g_cursor[NN];    // fill cursors
__device__ int    g_deg[NN];       // in-degree (excl. self-loop)
__device__ float  g_dis[NN];       // rsqrt(deg+1)
__device__ float2 g_t[2][NN];      // ping-pong: t = dis * (h @ W)
__device__ int    g_part[1024];    // scan partials
__device__ int    g_is64;

// ---- dtype sniff: int64 indices < 2^31 have all-zero odd 32-bit words -----
__global__ void k_detect(const unsigned int* __restrict__ w) {
    int lane = threadIdx.x;
    unsigned int acc = 0;
    for (int i = 0; i < 32; i++) acc |= w[2 * (lane * 32 + i) + 1];
    unsigned mask = __ballot_sync(0xFFFFFFFFu, acc != 0);
    if (lane == 0) g_is64 = (mask == 0) ? 1 : 0;
}

__global__ void k_zero() {
    int i = blockIdx.x * blockDim.x + threadIdx.x;
    if (i < NN) g_deg[i] = 0;
}

// count in-degree at dst (reads dst half of edge_index only)
__global__ void k_deg(const void* __restrict__ ei_raw) {
    int e = blockIdx.x * blockDim.x + threadIdx.x;
    if (e >= NE) return;
    int d;
    if (g_is64) d = (int)((const long long*)ei_raw)[NE + e];
    else        d = ((const int*)ei_raw)[NE + e];
    atomicAdd(&g_deg[d], 1);
}

// ---- 3-kernel exclusive scan of g_deg -> g_row ----------------------------
__global__ void k_scan1() {
    __shared__ int sm[256];
    int i = blockIdx.x * 256 + threadIdx.x;
    int v = (i < NN) ? g_deg[i] : 0;
    sm[threadIdx.x] = v;
    __syncthreads();
    for (int off = 1; off < 256; off <<= 1) {
        int t = (threadIdx.x >= off) ? sm[threadIdx.x - off] : 0;
        __syncthreads();
        sm[threadIdx.x] += t;
        __syncthreads();
    }
    if (i < NN) g_row[i] = sm[threadIdx.x] - v;      // exclusive within block
    if (threadIdx.x == 255) g_part[blockIdx.x] = sm[255];
}

__global__ void k_scan2() {   // one block of 1024, scans NB_N partials
    __shared__ int sm[1024];
    int t = threadIdx.x;
    int v = (t < NB_N) ? g_part[t] : 0;
    sm[t] = v;
    __syncthreads();
    for (int off = 1; off < 1024; off <<= 1) {
        int u = (t >= off) ? sm[t - off] : 0;
        __syncthreads();
        sm[t] += u;
        __syncthreads();
    }
    if (t < NB_N) g_part[t] = sm[t] - v;             // exclusive block offset
}

__global__ void k_scan3() {
    int i = blockIdx.x * blockDim.x + threadIdx.x;
    if (i < NN) {
        int r = g_row[i] + g_part[i >> 8];
        g_row[i] = r;
        g_cursor[i] = r;
    }
    if (i == 0) g_row[NN] = NE;
}

// scatter src ids into dst-grouped CSR
__global__ void k_fill(const void* __restrict__ ei_raw) {
    int e = blockIdx.x * blockDim.x + threadIdx.x;
    if (e >= NE) return;
    int s, d;
    if (g_is64) {
        const long long* ei = (const long long*)ei_raw;
        s = (int)ei[e];  d = (int)ei[NE + e];
    } else {
        const int* ei = (const int*)ei_raw;
        s = ei[e];       d = ei[NE + e];
    }
    int pos = atomicAdd(&g_cursor[d], 1);
    g_csr[pos] = s;
}

// dis = rsqrt(deg+1); t0 = dis * (x @ W0)
__global__ void k_init(const float* __restrict__ x, const float* __restrict__ Ws) {
    int n = blockIdx.x * blockDim.x + threadIdx.x;
    if (n >= NN) return;
    float ds = rsqrtf((float)(g_deg[n] + 1));
    g_dis[n] = ds;
    float w00 = __ldg(&Ws[0]), w01 = __ldg(&Ws[1]);
    float w10 = __ldg(&Ws[2]), w11 = __ldg(&Ws[3]);
    float hx = x[2 * n], hy = x[2 * n + 1];
    g_t[0][n] = make_float2(ds * (hx * w00 + hy * w10),
                            ds * (hx * w01 + hy * w11));
}

// Fused layer: acc = sum_{src->n} t[src];  h = dis*(acc + t[n]) + b
// then t_next = dis*(h @ W_next), or final transposed output.
__global__ void k_layer(const float* __restrict__ Ws, const float* __restrict__ bs,
                        int layer, int inbuf, float* __restrict__ out) {
    int n = blockIdx.x * blockDim.x + threadIdx.x;
    if (n >= NN) return;
    const float2* __restrict__ tin = g_t[inbuf];
    int beg = g_row[n], end = g_row[n + 1];

    float ax = 0.f, ay = 0.f;
    int j = beg;
    for (; j + 3 < end; j += 4) {
        int s0 = g_csr[j], s1 = g_csr[j + 1], s2 = g_csr[j + 2], s3 = g_csr[j + 3];
        float2 v0 = __ldg(&tin[s0]);
        float2 v1 = __ldg(&tin[s1]);
        float2 v2 = __ldg(&tin[s2]);
        float2 v3 = __ldg(&tin[s3]);
        ax += (v0.x + v1.x) + (v2.x + v3.x);
        ay += (v0.y + v1.y) + (v2.y + v3.y);
    }
    for (; j < end; ++j) {
        float2 v = __ldg(&tin[g_csr[j]]);
        ax += v.x;  ay += v.y;
    }

    float ds = g_dis[n];
    float2 ts = tin[n];                       // self-loop term
    float b0 = __ldg(&bs[layer * 2 + 0]);
    float b1 = __ldg(&bs[layer * 2 + 1]);
    float hx = ds * (ax + ts.x) + b0;
    float hy = ds * (ay + ts.y) + b1;

    if (layer == NL - 1) {
        out[n]      = hx;
        out[NN + n] = hy;
    } else {
        const float* W = Ws + (layer + 1) * 4;
        float w00 = __ldg(&W[0]), w01 = __ldg(&W[1]);
        float w10 = __ldg(&W[2]), w11 = __ldg(&W[3]);
        g_t[inbuf ^ 1][n] = make_float2(ds * (hx * w00 + hy * w10),
                                        ds * (hx * w01 + hy * w11));
    }
}

extern "C" void kernel_launch(void* const* d_in, const int* in_sizes, int n_in,
                              void* d_out, int out_size) {
    const float* x  = (const float*)d_in[0];
    const void*  ei = d_in[1];
    const float* Ws = (const float*)d_in[2];
    const float* bs = (const float*)d_in[3];
    float* out = (float*)d_out;

    const int TB = 256;
    const int NB_E = (NE + TB - 1) / TB;

    k_detect<<<1, 32>>>((const unsigned int*)ei);
    k_zero<<<NB_N, TB>>>();
    k_deg<<<NB_E, TB>>>(ei);
    k_scan1<<<NB_N, TB>>>();
    k_scan2<<<1, 1024>>>();
    k_scan3<<<NB_N, TB>>>();
    k_fill<<<NB_E, TB>>>(ei);
    k_init<<<NB_N, TB>>>(x, Ws);

    int inbuf = 0;
    for (int l = 0; l < NL; l++) {
        k_layer<<<NB_N, TB>>>(Ws, bs, l, inbuf, out);
        inbuf ^= 1;
    }
}

// round 3
// speedup vs baseline: 1.5536x; 1.0001x over previous
#include <cuda_runtime.h>
#include <cstdint>

#define NN 200000
#define NE 6400000
#define NL 10
#define NB_N 782          // ceil(NN/256)

// ---------------- scratch (static __device__, no allocs) -------------------
__device__ int    g_csr[NE];       // src ids, grouped by dst (25.6 MB)
__device__ int    g_row[NN + 1];   // CSR row pointers (exclusive prefix of deg)
__device__ int    g_cursor[NN];    // fill cursors
__device__ int    g_deg[NN];       // in-degree (excl. self-loop)
__device__ float  g_dis[NN];       // rsqrt(deg+1)
__device__ float2 g_t[2][NN];      // ping-pong: t = dis * (h @ W)
__device__ int    g_part[1024];    // scan partials
__device__ int    g_is64;

// ---- dtype sniff: int64 indices < 2^31 have all-zero odd 32-bit words -----
__global__ void k_detect(const unsigned int* __restrict__ w) {
    int lane = threadIdx.x;
    unsigned int acc = 0;
    for (int i = 0; i < 32; i++) acc |= w[2 * (lane * 32 + i) + 1];
    unsigned mask = __ballot_sync(0xFFFFFFFFu, acc != 0);
    if (lane == 0) g_is64 = (mask == 0) ? 1 : 0;
}

__global__ void k_zero() {
    int i = blockIdx.x * blockDim.x + threadIdx.x;
    if (i < NN) g_deg[i] = 0;
}

// count in-degree at dst (reads dst half of edge_index only)
__global__ void k_deg(const void* __restrict__ ei_raw) {
    int e = blockIdx.x * blockDim.x + threadIdx.x;
    if (e >= NE) return;
    int d;
    if (g_is64) d = (int)((const long long*)ei_raw)[NE + e];
    else        d = ((const int*)ei_raw)[NE + e];
    atomicAdd(&g_deg[d], 1);
}

// ---- 3-kernel exclusive scan of g_deg -> g_row ----------------------------
__global__ void k_scan1() {
    __shared__ int sm[256];
    int i = blockIdx.x * 256 + threadIdx.x;
    int v = (i < NN) ? g_deg[i] : 0;
    sm[threadIdx.x] = v;
    __syncthreads();
    for (int off = 1; off < 256; off <<= 1) {
        int t = (threadIdx.x >= off) ? sm[threadIdx.x - off] : 0;
        __syncthreads();
        sm[threadIdx.x] += t;
        __syncthreads();
    }
    if (i < NN) g_row[i] = sm[threadIdx.x] - v;      // exclusive within block
    if (threadIdx.x == 255) g_part[blockIdx.x] = sm[255];
}

__global__ void k_scan2() {   // one block of 1024, scans NB_N partials
    __shared__ int sm[1024];
    int t = threadIdx.x;
    int v = (t < NB_N) ? g_part[t] : 0;
    sm[t] = v;
    __syncthreads();
    for (int off = 1; off < 1024; off <<= 1) {
        int u = (t >= off) ? sm[t - off] : 0;
        __syncthreads();
        sm[t] += u;
        __syncthreads();
    }
    if (t < NB_N) g_part[t] = sm[t] - v;             // exclusive block offset
}

__global__ void k_scan3() {
    int i = blockIdx.x * blockDim.x + threadIdx.x;
    if (i < NN) {
        int r = g_row[i] + g_part[i >> 8];
        g_row[i] = r;
        g_cursor[i] = r;
    }
    if (i == 0) g_row[NN] = NE;
}

// scatter src ids into dst-grouped CSR
__global__ void k_fill(const void* __restrict__ ei_raw) {
    int e = blockIdx.x * blockDim.x + threadIdx.x;
    if (e >= NE) return;
    int s, d;
    if (g_is64) {
        const long long* ei = (const long long*)ei_raw;
        s = (int)ei[e];  d = (int)ei[NE + e];
    } else {
        const int* ei = (const int*)ei_raw;
        s = ei[e];       d = ei[NE + e];
    }
    int pos = atomicAdd(&g_cursor[d], 1);
    g_csr[pos] = s;
}

// dis = rsqrt(deg+1); t0 = dis * (x @ W0)
__global__ void k_init(const float* __restrict__ x, const float* __restrict__ Ws) {
    int n = blockIdx.x * blockDim.x + threadIdx.x;
    if (n >= NN) return;
    float ds = rsqrtf((float)(g_deg[n] + 1));
    g_dis[n] = ds;
    float w00 = __ldg(&Ws[0]), w01 = __ldg(&Ws[1]);
    float w10 = __ldg(&Ws[2]), w11 = __ldg(&Ws[3]);
    float hx = x[2 * n], hy = x[2 * n + 1];
    g_t[0][n] = make_float2(ds * (hx * w00 + hy * w10),
                            ds * (hx * w01 + hy * w11));
}

// Fused layer: acc = sum_{src->n} t[src];  h = dis*(acc + t[n]) + b
// then t_next = dis*(h @ W_next), or final transposed output.
__global__ void k_layer(const float* __restrict__ Ws, const float* __restrict__ bs,
                        int layer, int inbuf, float* __restrict__ out) {
    int n = blockIdx.x * blockDim.x + threadIdx.x;
    if (n >= NN) return;
    const float2* __restrict__ tin = g_t[inbuf];
    int beg = g_row[n], end = g_row[n + 1];

    float ax = 0.f, ay = 0.f;
    int j = beg;
    for (; j + 3 < end; j += 4) {
        int s0 = g_csr[j], s1 = g_csr[j + 1], s2 = g_csr[j + 2], s3 = g_csr[j + 3];
        float2 v0 = __ldg(&tin[s0]);
        float2 v1 = __ldg(&tin[s1]);
        float2 v2 = __ldg(&tin[s2]);
        float2 v3 = __ldg(&tin[s3]);
        ax += (v0.x + v1.x) + (v2.x + v3.x);
        ay += (v0.y + v1.y) + (v2.y + v3.y);
    }
    for (; j < end; ++j) {
        float2 v = __ldg(&tin[g_csr[j]]);
        ax += v.x;  ay += v.y;
    }

    float ds = g_dis[n];
    float2 ts = tin[n];                       // self-loop term
    float b0 = __ldg(&bs[layer * 2 + 0]);
    float b1 = __ldg(&bs[layer * 2 + 1]);
    float hx = ds * (ax + ts.x) + b0;
    float hy = ds * (ay + ts.y) + b1;

    if (layer == NL - 1) {
        out[n]      = hx;
        out[NN + n] = hy;
    } else {
        const float* W = Ws + (layer + 1) * 4;
        float w00 = __ldg(&W[0]), w01 = __ldg(&W[1]);
        float w10 = __ldg(&W[2]), w11 = __ldg(&W[3]);
        g_t[inbuf ^ 1][n] = make_float2(ds * (hx * w00 + hy * w10),
                                        ds * (hx * w01 + hy * w11));
    }
}

extern "C" void kernel_launch(void* const* d_in, const int* in_sizes, int n_in,
                              void* d_out, int out_size) {
    const float* x  = (const float*)d_in[0];
    const void*  ei = d_in[1];
    const float* Ws = (const float*)d_in[2];
    const float* bs = (const float*)d_in[3];
    float* out = (float*)d_out;

    const int TB = 256;
    const int NB_E = (NE + TB - 1) / TB;

    k_detect<<<1, 32>>>((const unsigned int*)ei);
    k_zero<<<NB_N, TB>>>();
    k_deg<<<NB_E, TB>>>(ei);
    k_scan1<<<NB_N, TB>>>();
    k_scan2<<<1, 1024>>>();
    k_scan3<<<NB_N, TB>>>();
    k_fill<<<NB_E, TB>>>(ei);
    k_init<<<NB_N, TB>>>(x, Ws);

    int inbuf = 0;
    for (int l = 0; l < NL; l++) {
        k_layer<<<NB_N, TB>>>(Ws, bs, l, inbuf, out);
        inbuf ^= 1;
    }
}